// round 6
// baseline (speedup 1.0000x reference)
#include <cuda_runtime.h>
#include <string.h>

#define Bdim 512
#define Ldim 512
#define Tdim 128
#define START_TAG 126
#define STOP_TAG 127
#define NEGV (-10000.0f)
#define LOG2E 1.4426950408889634f
#define LN2   0.6931471805599453f
#define PF 8              // emission prefetch depth / unroll factor
#define NWORK 304         // persistent CTAs (2 per SM)
#define NTHR 256          // threads per CTA (split-K: 2 threads per state)

__device__ float g_partial[Bdim];     // per-batch forward - gold
__device__ int   g_counter;           // work queue head
__device__ int   g_done;              // completion counter
__device__ int   g_order[Bdim];       // batch ids sorted by len desc

__device__ __forceinline__ void fma2(unsigned long long& d,
                                     unsigned long long a,
                                     unsigned long long b) {
    asm("fma.rn.f32x2 %0, %1, %2, %0;" : "+l"(d) : "l"(a), "l"(b));
}
__device__ __forceinline__ float rcp_fast(float x) {
    float r;
    asm("rcp.approx.f32 %0, %1;" : "=f"(r) : "f"(x));
    return r;
}

// partial[t,h] = sum_{p in half} et[t,p] * gs_half[p]  (64-wide, et packed f32x2)
__device__ __forceinline__ float matvec64(const float* gs_half,
                                          const unsigned long long* et) {
    const ulonglong2* g2 = reinterpret_cast<const ulonglong2*>(gs_half);
    unsigned long long a0 = 0, a1 = 0, a2 = 0, a3 = 0;
    #pragma unroll
    for (int k = 0; k < 16; k += 2) {
        ulonglong2 u = g2[k];
        ulonglong2 v = g2[k + 1];
        fma2(a0, et[2 * k + 0], u.x);
        fma2(a1, et[2 * k + 1], u.y);
        fma2(a2, et[2 * k + 2], v.x);
        fma2(a3, et[2 * k + 3], v.y);
    }
    float2 f0, f1, f2, f3;
    memcpy(&f0, &a0, 8); memcpy(&f1, &a1, 8);
    memcpy(&f2, &a2, 8); memcpy(&f3, &a3, 8);
    return ((f0.x + f0.y) + (f1.x + f1.y)) + ((f2.x + f2.y) + (f3.x + f3.y));
}

// terminal LSE + gold score with 256 threads; fv valid in h==0 threads (t = tid&127)
__device__ __forceinline__ float finish_batch(
    float fv, int len, int b, int tid, int t, int h, int lane, int warp,
    const float* __restrict__ feats, const float* __restrict__ trans,
    const int* __restrict__ tags, float* smax, float* ssum)
{
    float term = (h == 0) ? (fv + trans[START_TAG * Tdim + t]) : NEGV;
    float m2 = term;
    #pragma unroll
    for (int o = 16; o > 0; o >>= 1)
        m2 = fmaxf(m2, __shfl_xor_sync(0xffffffffu, m2, o));
    if (lane == 0) smax[warp] = m2;
    __syncthreads();
    m2 = fmaxf(fmaxf(smax[0], smax[1]), fmaxf(smax[2], smax[3]));

    float ex = (h == 0) ? exp2f((term - m2) * LOG2E) : 0.0f;
    #pragma unroll
    for (int o = 16; o > 0; o >>= 1)
        ex += __shfl_xor_sync(0xffffffffu, ex, o);
    if (lane == 0) ssum[warp] = ex;
    __syncthreads();
    float fwd = m2 + __logf(((ssum[0] + ssum[1]) + (ssum[2] + ssum[3])));
    __syncthreads();

    float acc = 0.f;
    const int* tg = tags + b * Ldim;
    for (int j = tid; j <= len; j += NTHR) {
        int pa, pb;
        if (j == 0)        { pa = START_TAG;   pb = tg[0];    }
        else if (j == len) { pa = tg[len - 1]; pb = STOP_TAG; }
        else               { pa = tg[j - 1];   pb = tg[j];    }
        acc += trans[pb * Tdim + pa];
    }
    for (int i = tid; i < len; i += NTHR) {
        int tag = tg[i];
        acc += feats[((size_t)b * Ldim + i) * Tdim + tag];
    }
    #pragma unroll
    for (int o = 16; o > 0; o >>= 1)
        acc += __shfl_xor_sync(0xffffffffu, acc, o);
    if (lane == 0) ssum[warp] = acc;
    __syncthreads();
    float gold = ((ssum[0] + ssum[1]) + (ssum[2] + ssum[3]))
               + ((ssum[4] + ssum[5]) + (ssum[6] + ssum[7]));
    __syncthreads();
    return fwd - gold;
}

// rank batches by length (desc, stable) + reset counters. grid 8 x 64
__global__ __launch_bounds__(64) void crf_schedule_kernel(const int* __restrict__ lens)
{
    __shared__ int sl[Bdim];
    const int tb = threadIdx.x;
    for (int k = tb; k < Bdim; k += 64) sl[k] = lens[k];
    __syncthreads();
    const int me = blockIdx.x * 64 + tb;
    const int myl = sl[me];
    int rank = 0;
    #pragma unroll 8
    for (int j = 0; j < Bdim; j++) {
        int lj = sl[j];
        rank += (lj > myl) || (lj == myl && j < me);
    }
    g_order[rank] = me;
    if (me == 0) { g_counter = NWORK; g_done = 0; }
}

__global__ __launch_bounds__(NTHR, 2) void crf_batch_kernel(
    const float* __restrict__ feats,        // [B, L, T]
    const float* __restrict__ trans,        // [T, T]  trans[next, prev]
    const int*   __restrict__ tags,         // [B, L]
    const int*   __restrict__ lens,         // [B]
    float*       __restrict__ out)
{
    const int tid  = threadIdx.x;
    const int t    = tid & (Tdim - 1);      // state owned
    const int h    = tid >> 7;              // K-half owned
    const int lane = tid & 31;
    const int warp = tid >> 5;

    __shared__ __align__(16) float gs[2][Tdim];   // normalized G, double-buffered
    __shared__ __align__(16) float spart[Tdim];   // h=1 partial sums
    __shared__ float sh_w[2];                     // thread0's unnormalized update
    __shared__ float smax[8];
    __shared__ float ssum[8];
    __shared__ int   sh_job;
    __shared__ int   sh_last;

    // ---- precompute exp(trans[t, h*64 : h*64+64]) packed f32x2 (32 u64 regs) ----
    unsigned long long et[Tdim / 4];
    {
        const float4* trow =
            reinterpret_cast<const float4*>(trans + t * Tdim + h * (Tdim / 2));
        #pragma unroll
        for (int k = 0; k < Tdim / 8; k++) {
            float4 v = trow[k];
            float2 lo = make_float2(exp2f(v.x * LOG2E), exp2f(v.y * LOG2E));
            float2 hi = make_float2(exp2f(v.z * LOG2E), exp2f(v.w * LOG2E));
            memcpy(&et[2 * k + 0], &lo, 8);
            memcpy(&et[2 * k + 1], &hi, 8);
        }
    }

    int job = blockIdx.x;
    while (job < Bdim) {
        const int b   = g_order[job];
        const int len = lens[b];
        const int lenm1 = len - 1;

        if (h == 0) gs[0][t] = (t == START_TAG) ? 1.0f : 0.0f;
        if (tid == 0) { sh_w[0] = 1.0f; }
        float Gcur = (t == START_TAG) ? 1.0f : 0.0f;
        float Macc = 0.0f;                       // accumulated shift (log2)

        const float* emit = feats + (size_t)b * Ldim * Tdim + t;

        // emission prefetch ring: only h==0 warps maintain/use it
        float ee[PF];
        if (h == 0) {
            #pragma unroll
            for (int k = 0; k < PF; k++)
                ee[k] = exp2f(emit[min(k, lenm1) * Tdim] * LOG2E);
        }

        __syncthreads();

        const int len_pad = (len + PF - 1) & ~(PF - 1);
        for (int i0 = 0; i0 < len_pad; i0 += PF) {
            #pragma unroll
            for (int j = 0; j < PF; j++) {
                const int i = i0 + j;
                const int p = i & 1;
                const bool act = (i < len);          // block-uniform

                float w = sh_w[p];
                float r = rcp_fast(w);

                float partial = matvec64(gs[p] + h * (Tdim / 2), et);
                if (h == 1) {
                    spart[t] = partial;
                } else {
                    // prefetch exp(emit) for step i+PF while partial lands
                    float ecur = ee[j];
                    ee[j] = exp2f(emit[min(i + PF, lenm1) * Tdim] * LOG2E);
                    ee[j] = act ? ee[j] : ee[j];     // keep ring uniform
                    if (act) {
                        // stash current emission in 'w' slot reuse below
                        // (ecur used after barrier)
                        Macc += __log2f(w);
                    }
                    // carry ecur across the barrier in a register
                    spart[t] = spart[t];             // no-op to keep layout
                    // store ecur in Gcur? no — just recompute path below
                    // use local:
                    // (handled after barrier via 'ecur' still live)
                    __syncthreads();                 // barrier 1: partials ready
                    float s = partial + spart[t];
                    if (act) {
                        float u = s * ecur;
                        float G = u * r;
                        gs[p ^ 1][t] = G;
                        if (tid == 0) sh_w[p ^ 1] = u;
                        Gcur = G;
                    }
                    __syncthreads();                 // barrier 2: gs published
                    continue;
                }
                __syncthreads();                     // barrier 1 (h==1 path)
                __syncthreads();                     // barrier 2 (h==1 path)
            }
        }

        // fv[t] = ln2 * (log2(G) + Macc); valid in h==0 threads
        float fv = (__log2f(Gcur) + Macc) * LN2;

        float res = finish_batch(fv, len, b, tid, t, h, lane, warp,
                                 feats, trans, tags, smax, ssum);
        if (tid == 0) {
            g_partial[b] = res;
            sh_job = atomicAdd(&g_counter, 1);
        }
        __syncthreads();
        job = sh_job;
        __syncthreads();
    }

    // ---- fused final reduction: last CTA to finish computes the mean ----
    __threadfence();
    if (tid == 0) sh_last = atomicAdd(&g_done, 1);
    __syncthreads();
    if (sh_last == NWORK - 1) {
        __threadfence();
        float v = 0.f;
        #pragma unroll
        for (int k = 0; k < Bdim / NTHR; k++)
            v += g_partial[k * NTHR + tid];
        #pragma unroll
        for (int o = 16; o > 0; o >>= 1)
            v += __shfl_xor_sync(0xffffffffu, v, o);
        if (lane == 0) ssum[warp] = v;
        __syncthreads();
        if (tid == 0)
            out[0] = (((ssum[0] + ssum[1]) + (ssum[2] + ssum[3]))
                    + ((ssum[4] + ssum[5]) + (ssum[6] + ssum[7])))
                     * (1.0f / (float)Bdim);
    }
}

extern "C" void kernel_launch(void* const* d_in, const int* in_sizes, int n_in,
                              void* d_out, int out_size)
{
    const float* feats = (const float*)d_in[0];
    const float* trans = (const float*)d_in[1];
    const int*   tags  = (const int*)d_in[2];
    const int*   lens  = (const int*)d_in[3];
    float* out = (float*)d_out;

    crf_schedule_kernel<<<8, 64>>>(lens);
    crf_batch_kernel<<<NWORK, NTHR>>>(feats, trans, tags, lens, out);
}

// round 7
// speedup vs baseline: 1.1647x; 1.1647x over previous
#include <cuda_runtime.h>
#include <string.h>

#define Bdim 512
#define Ldim 512
#define Tdim 128
#define START_TAG 126
#define STOP_TAG 127
#define NEGV (-10000.0f)
#define LOG2E 1.4426950408889634f
#define LN2   0.6931471805599453f
#define PF 8              // emission prefetch depth / unroll factor
#define NWORK 456         // persistent CTAs (3 per SM)

__device__ float g_partial[Bdim];     // per-batch forward - gold
__device__ int   g_counter;           // work queue head
__device__ int   g_done;              // completion counter
__device__ int   g_order[Bdim];       // batch ids sorted by len desc

__device__ __forceinline__ void fma2(unsigned long long& d,
                                     unsigned long long a,
                                     unsigned long long b) {
    asm("fma.rn.f32x2 %0, %1, %2, %0;" : "+l"(d) : "l"(a), "l"(b));
}
__device__ __forceinline__ float rcp_fast(float x) {
    float r;
    asm("rcp.approx.f32 %0, %1;" : "=f"(r) : "f"(x));
    return r;
}

// s[t] = sum_p et[t,p] * gs[p], et packed f32x2 in registers
__device__ __forceinline__ float matvec128(const float* gs,
                                           const unsigned long long* et) {
    const ulonglong2* g2 = reinterpret_cast<const ulonglong2*>(gs);
    unsigned long long a0 = 0, a1 = 0, a2 = 0, a3 = 0;
    #pragma unroll
    for (int k = 0; k < 32; k += 2) {
        ulonglong2 u = g2[k];
        ulonglong2 v = g2[k + 1];
        fma2(a0, et[2 * k + 0], u.x);
        fma2(a1, et[2 * k + 1], u.y);
        fma2(a2, et[2 * k + 2], v.x);
        fma2(a3, et[2 * k + 3], v.y);
    }
    float2 f0, f1, f2, f3;
    memcpy(&f0, &a0, 8); memcpy(&f1, &a1, 8);
    memcpy(&f2, &a2, 8); memcpy(&f3, &a3, 8);
    return ((f0.x + f0.y) + (f1.x + f1.y)) + ((f2.x + f2.y) + (f3.x + f3.y));
}

// terminal LSE + gold score; returns forward_score - gold_score (all threads)
__device__ __forceinline__ float finish_batch(
    float fv, int len, int b, int t, int lane, int warp,
    const float* __restrict__ feats, const float* __restrict__ trans,
    const int* __restrict__ tags, float* smax, float* ssum)
{
    float term = fv + trans[START_TAG * Tdim + t];
    float m2 = term;
    #pragma unroll
    for (int o = 16; o > 0; o >>= 1)
        m2 = fmaxf(m2, __shfl_xor_sync(0xffffffffu, m2, o));
    if (lane == 0) smax[warp] = m2;
    __syncthreads();
    m2 = fmaxf(fmaxf(smax[0], smax[1]), fmaxf(smax[2], smax[3]));

    float ex = exp2f((term - m2) * LOG2E);
    #pragma unroll
    for (int o = 16; o > 0; o >>= 1)
        ex += __shfl_xor_sync(0xffffffffu, ex, o);
    if (lane == 0) ssum[warp] = ex;
    __syncthreads();
    float fwd = m2 + __logf((ssum[0] + ssum[1]) + (ssum[2] + ssum[3]));
    __syncthreads();

    float acc = 0.f;
    const int* tg = tags + b * Ldim;
    for (int j = t; j <= len; j += Tdim) {
        int pa, pb;
        if (j == 0)        { pa = START_TAG;   pb = tg[0];    }
        else if (j == len) { pa = tg[len - 1]; pb = STOP_TAG; }
        else               { pa = tg[j - 1];   pb = tg[j];    }
        acc += trans[pb * Tdim + pa];
    }
    for (int i = t; i < len; i += Tdim) {
        int tag = tg[i];
        acc += feats[((size_t)b * Ldim + i) * Tdim + tag];
    }
    #pragma unroll
    for (int o = 16; o > 0; o >>= 1)
        acc += __shfl_xor_sync(0xffffffffu, acc, o);
    if (lane == 0) ssum[warp] = acc;
    __syncthreads();
    float gold = (ssum[0] + ssum[1]) + (ssum[2] + ssum[3]);
    __syncthreads();
    return fwd - gold;
}

// rank batches by length (desc, stable) + reset counters. grid 8 x 64
__global__ __launch_bounds__(64) void crf_schedule_kernel(const int* __restrict__ lens)
{
    __shared__ int sl[Bdim];
    const int tb = threadIdx.x;
    for (int k = tb; k < Bdim; k += 64) sl[k] = lens[k];
    __syncthreads();
    const int me = blockIdx.x * 64 + tb;
    const int myl = sl[me];
    int rank = 0;
    #pragma unroll 8
    for (int j = 0; j < Bdim; j++) {
        int lj = sl[j];
        rank += (lj > myl) || (lj == myl && j < me);
    }
    g_order[rank] = me;
    if (me == 0) { g_counter = NWORK; g_done = 0; }
}

__global__ __launch_bounds__(Tdim, 3) void crf_batch_kernel(
    const float* __restrict__ feats,        // [B, L, T]
    const float* __restrict__ trans,        // [T, T]  trans[next, prev]
    const int*   __restrict__ tags,         // [B, L]
    const int*   __restrict__ lens,         // [B]
    float*       __restrict__ out)
{
    const int t    = threadIdx.x;           // this thread owns state 't'
    const int lane = t & 31;
    const int warp = t >> 5;

    __shared__ __align__(16) float gs[2][Tdim];  // UNNORMALIZED v_i, double-buffered
    __shared__ float smax[4];
    __shared__ float ssum[4];
    __shared__ int   sh_job;
    __shared__ int   sh_last;

    // ---- precompute exp(trans[t, :]) packed f32x2 into registers ----
    unsigned long long et[Tdim / 2];
    {
        const float4* trow = reinterpret_cast<const float4*>(trans + t * Tdim);
        #pragma unroll
        for (int k = 0; k < Tdim / 4; k++) {
            float4 v = trow[k];
            float2 lo = make_float2(exp2f(v.x * LOG2E), exp2f(v.y * LOG2E));
            float2 hi = make_float2(exp2f(v.z * LOG2E), exp2f(v.w * LOG2E));
            memcpy(&et[2 * k + 0], &lo, 8);
            memcpy(&et[2 * k + 1], &hi, 8);
        }
    }
    // et[t, START] for the peeled first step (START=126 -> pair 63, low half)
    float etSTART;
    {
        float2 pr;
        memcpy(&pr, &et[START_TAG / 2], 8);
        etSTART = pr.x;
    }

    int job = blockIdx.x;
    while (job < Bdim) {
        const int b   = g_order[job];
        const int len = lens[b];
        const int lenm1 = len - 1;

        const float* emit = feats + (size_t)b * Ldim * Tdim + t;

        // emission prefetch ring: ee[k] = exp(emit at step k)
        float ee[PF];
        #pragma unroll
        for (int k = 0; k < PF; k++)
            ee[k] = exp2f(emit[min(k, lenm1) * Tdim] * LOG2E);

        // ---- peeled step 0: v_1[t] = ee_0[t] * exp(trans[t, START]) ----
        float Gcur = ee[0] * etSTART;          // v_1, scale C_1 = 1
        float Macc = 0.0f;                     // accumulated log2 scale
        gs[1][t] = Gcur;                       // step i reads gs[i&1]
        ee[0] = exp2f(emit[min(PF, lenm1) * Tdim] * LOG2E);
        __syncthreads();

        // ---- peeled steps 1..7 ----
        #pragma unroll
        for (int j = 1; j < PF; j++) {
            const int i = j;
            const int p = i & 1;
            const bool act = (i < len);        // block-uniform

            float w = gs[p][0];                // broadcast LDS, always > 0
            float r = rcp_fast(w);
            float f = ee[j] * r;
            ee[j] = exp2f(emit[min(i + PF, lenm1) * Tdim] * LOG2E);

            float s = matvec128(gs[p], et);
            if (act) {
                float u = s * f;
                gs[p ^ 1][t] = u;
                Gcur = u;
                Macc += __log2f(w);
            }
            __syncthreads();
        }

        // ---- main loop, blocks of PF ----
        for (int i0 = PF; i0 < len; i0 += PF) {
            #pragma unroll
            for (int j = 0; j < PF; j++) {
                const int i = i0 + j;
                const int p = i & 1;
                const bool act = (i < len);    // block-uniform

                float w = gs[p][0];
                float r = rcp_fast(w);
                float f = ee[j] * r;
                ee[j] = exp2f(emit[min(i + PF, lenm1) * Tdim] * LOG2E);

                float s = matvec128(gs[p], et);
                if (act) {
                    float u = s * f;
                    gs[p ^ 1][t] = u;
                    Gcur = u;
                    Macc += __log2f(w);
                }
                __syncthreads();
            }
        }

        // fv[t] = ln2 * (log2(v_len) + Macc); v==0 (START row) -> -inf, OK in LSE
        float fv = (__log2f(Gcur) + Macc) * LN2;

        float res = finish_batch(fv, len, b, t, lane, warp,
                                 feats, trans, tags, smax, ssum);
        if (t == 0) {
            g_partial[b] = res;
            sh_job = atomicAdd(&g_counter, 1);
        }
        __syncthreads();
        job = sh_job;
        __syncthreads();
    }

    // ---- fused final reduction: last CTA to finish computes the mean ----
    __threadfence();
    if (t == 0) sh_last = atomicAdd(&g_done, 1);
    __syncthreads();
    if (sh_last == NWORK - 1) {
        __threadfence();
        float v = 0.f;
        #pragma unroll
        for (int k = 0; k < Bdim / Tdim; k++)
            v += g_partial[k * Tdim + t];
        #pragma unroll
        for (int o = 16; o > 0; o >>= 1)
            v += __shfl_xor_sync(0xffffffffu, v, o);
        if (lane == 0) ssum[warp] = v;
        __syncthreads();
        if (t == 0)
            out[0] = ((ssum[0] + ssum[1]) + (ssum[2] + ssum[3])) * (1.0f / (float)Bdim);
    }
}

extern "C" void kernel_launch(void* const* d_in, const int* in_sizes, int n_in,
                              void* d_out, int out_size)
{
    const float* feats = (const float*)d_in[0];
    const float* trans = (const float*)d_in[1];
    const int*   tags  = (const int*)d_in[2];
    const int*   lens  = (const int*)d_in[3];
    float* out = (float*)d_out;

    crf_schedule_kernel<<<8, 64>>>(lens);
    crf_batch_kernel<<<NWORK, Tdim>>>(feats, trans, tags, lens, out);
}

// round 8
// speedup vs baseline: 1.1771x; 1.0106x over previous
#include <cuda_runtime.h>
#include <string.h>

#define Bdim 512
#define Ldim 512
#define Tdim 128
#define START_TAG 126
#define STOP_TAG 127
#define NEGV (-10000.0f)
#define LOG2E 1.4426950408889634f
#define LN2   0.6931471805599453f
#define PF 8              // emission prefetch depth / unroll factor
#define NWORK 152         // persistent CTAs (1 per SM, pair = 2 streams/SMSP)
#define NJOBS (Bdim / 2)  // pair jobs (adjacent LPT ranks)

__device__ float g_partial[Bdim];     // per-batch forward - gold
__device__ int   g_counter;           // work queue head
__device__ int   g_done;              // completion counter
__device__ int   g_order[Bdim];       // batch ids sorted by len desc

__device__ __forceinline__ void fma2(unsigned long long& d,
                                     unsigned long long a,
                                     unsigned long long b) {
    asm("fma.rn.f32x2 %0, %1, %2, %0;" : "+l"(d) : "l"(a), "l"(b));
}
__device__ __forceinline__ float rcp_fast(float x) {
    float r;
    asm("rcp.approx.f32 %0, %1;" : "=f"(r) : "f"(x));
    return r;
}

// s[t] = sum_p et[t,p] * gs[p], et packed f32x2 in registers
__device__ __forceinline__ float matvec128(const float* gs,
                                           const unsigned long long* et) {
    const ulonglong2* g2 = reinterpret_cast<const ulonglong2*>(gs);
    unsigned long long a0 = 0, a1 = 0, a2 = 0, a3 = 0;
    #pragma unroll
    for (int k = 0; k < 32; k += 2) {
        ulonglong2 u = g2[k];
        ulonglong2 v = g2[k + 1];
        fma2(a0, et[2 * k + 0], u.x);
        fma2(a1, et[2 * k + 1], u.y);
        fma2(a2, et[2 * k + 2], v.x);
        fma2(a3, et[2 * k + 3], v.y);
    }
    float2 f0, f1, f2, f3;
    memcpy(&f0, &a0, 8); memcpy(&f1, &a1, 8);
    memcpy(&f2, &a2, 8); memcpy(&f3, &a3, 8);
    return ((f0.x + f0.y) + (f1.x + f1.y)) + ((f2.x + f2.y) + (f3.x + f3.y));
}

// terminal LSE + gold score; returns forward_score - gold_score (all threads)
__device__ __forceinline__ float finish_batch(
    float fv, int len, int b, int t, int lane, int warp,
    const float* __restrict__ feats, const float* __restrict__ trans,
    const int* __restrict__ tags, float* smax, float* ssum)
{
    float term = fv + trans[START_TAG * Tdim + t];
    float m2 = term;
    #pragma unroll
    for (int o = 16; o > 0; o >>= 1)
        m2 = fmaxf(m2, __shfl_xor_sync(0xffffffffu, m2, o));
    if (lane == 0) smax[warp] = m2;
    __syncthreads();
    m2 = fmaxf(fmaxf(smax[0], smax[1]), fmaxf(smax[2], smax[3]));

    float ex = exp2f((term - m2) * LOG2E);
    #pragma unroll
    for (int o = 16; o > 0; o >>= 1)
        ex += __shfl_xor_sync(0xffffffffu, ex, o);
    if (lane == 0) ssum[warp] = ex;
    __syncthreads();
    float fwd = m2 + __logf((ssum[0] + ssum[1]) + (ssum[2] + ssum[3]));
    __syncthreads();

    float acc = 0.f;
    const int* tg = tags + b * Ldim;
    for (int j = t; j <= len; j += Tdim) {
        int pa, pb;
        if (j == 0)        { pa = START_TAG;   pb = tg[0];    }
        else if (j == len) { pa = tg[len - 1]; pb = STOP_TAG; }
        else               { pa = tg[j - 1];   pb = tg[j];    }
        acc += trans[pb * Tdim + pa];
    }
    for (int i = t; i < len; i += Tdim) {
        int tag = tg[i];
        acc += feats[((size_t)b * Ldim + i) * Tdim + tag];
    }
    #pragma unroll
    for (int o = 16; o > 0; o >>= 1)
        acc += __shfl_xor_sync(0xffffffffu, acc, o);
    if (lane == 0) ssum[warp] = acc;
    __syncthreads();
    float gold = (ssum[0] + ssum[1]) + (ssum[2] + ssum[3]);
    __syncthreads();
    return fwd - gold;
}

// rank batches by length (desc, stable) + reset counters. grid 8 x 64
__global__ __launch_bounds__(64) void crf_schedule_kernel(const int* __restrict__ lens)
{
    __shared__ int sl[Bdim];
    const int tb = threadIdx.x;
    for (int k = tb; k < Bdim; k += 64) sl[k] = lens[k];
    __syncthreads();
    const int me = blockIdx.x * 64 + tb;
    const int myl = sl[me];
    int rank = 0;
    #pragma unroll 8
    for (int j = 0; j < Bdim; j++) {
        int lj = sl[j];
        rank += (lj > myl) || (lj == myl && j < me);
    }
    g_order[rank] = me;
    if (me == 0) { g_counter = NWORK; g_done = 0; }
}

__global__ __launch_bounds__(Tdim) void crf_batch_kernel(
    const float* __restrict__ feats,        // [B, L, T]
    const float* __restrict__ trans,        // [T, T]  trans[next, prev]
    const int*   __restrict__ tags,         // [B, L]
    const int*   __restrict__ lens,         // [B]
    float*       __restrict__ out)
{
    const int t    = threadIdx.x;           // this thread owns state 't'
    const int lane = t & 31;
    const int warp = t >> 5;

    __shared__ __align__(16) float gs1[2][Tdim]; // unnormalized v_i, batch 1
    __shared__ __align__(16) float gs2[2][Tdim]; // unnormalized v_i, batch 2
    __shared__ float smax[4];
    __shared__ float ssum[4];
    __shared__ int   sh_job;
    __shared__ int   sh_last;

    // ---- precompute exp(trans[t, :]) packed f32x2 (shared by the pair) ----
    unsigned long long et[Tdim / 2];
    {
        const float4* trow = reinterpret_cast<const float4*>(trans + t * Tdim);
        #pragma unroll
        for (int k = 0; k < Tdim / 4; k++) {
            float4 v = trow[k];
            float2 lo = make_float2(exp2f(v.x * LOG2E), exp2f(v.y * LOG2E));
            float2 hi = make_float2(exp2f(v.z * LOG2E), exp2f(v.w * LOG2E));
            memcpy(&et[2 * k + 0], &lo, 8);
            memcpy(&et[2 * k + 1], &hi, 8);
        }
    }
    // et[t, START]  (START=126 -> u64 pair 63, low half)
    float etSTART;
    {
        float2 pr;
        memcpy(&pr, &et[START_TAG / 2], 8);
        etSTART = pr.x;
    }

    int job = blockIdx.x;
    while (job < NJOBS) {
        const int b1 = g_order[2 * job];
        const int b2 = g_order[2 * job + 1];
        const int len1 = lens[b1];
        const int len2 = lens[b2];
        const int l1m = len1 - 1, l2m = len2 - 1;
        const int lenmax = max(len1, len2);

        const float* emit1 = feats + (size_t)b1 * Ldim * Tdim + t;
        const float* emit2 = feats + (size_t)b2 * Ldim * Tdim + t;

        // emission prefetch rings: ee[k] = exp(emit at step k)
        float ee1[PF], ee2[PF];
        #pragma unroll
        for (int k = 0; k < PF; k++) {
            ee1[k] = exp2f(emit1[min(k, l1m) * Tdim] * LOG2E);
            ee2[k] = exp2f(emit2[min(k, l2m) * Tdim] * LOG2E);
        }

        // ---- peeled step 0: v_1[t] = ee_0[t] * exp(trans[t, START]) ----
        float G1 = ee1[0] * etSTART;
        float G2 = ee2[0] * etSTART;
        float Ma1 = 0.0f, Ma2 = 0.0f;            // accumulated log2 scales
        gs1[1][t] = G1;                          // step i reads gs[i&1]
        gs2[1][t] = G2;
        ee1[0] = exp2f(emit1[min(PF, l1m) * Tdim] * LOG2E);
        ee2[0] = exp2f(emit2[min(PF, l2m) * Tdim] * LOG2E);
        __syncthreads();

        // ---- peeled steps 1..PF-1 ----
        #pragma unroll
        for (int j = 1; j < PF; j++) {
            const int i = j;
            const int p = i & 1;
            const bool a1 = (i < len1);          // block-uniform
            const bool a2 = (i < len2);

            float w1 = gs1[p][0];                // broadcast LDS (stale = prev v[0])
            float w2 = gs2[p][0];
            float r1 = rcp_fast(w1), r2 = rcp_fast(w2);
            float f1 = ee1[j] * r1,  f2 = ee2[j] * r2;
            ee1[j] = exp2f(emit1[min(i + PF, l1m) * Tdim] * LOG2E);
            ee2[j] = exp2f(emit2[min(i + PF, l2m) * Tdim] * LOG2E);

            float s1 = matvec128(gs1[p], et);    // two independent chains
            float s2 = matvec128(gs2[p], et);
            if (a1) { float u = s1 * f1; gs1[p ^ 1][t] = u; G1 = u; Ma1 += __log2f(w1); }
            if (a2) { float u = s2 * f2; gs2[p ^ 1][t] = u; G2 = u; Ma2 += __log2f(w2); }
            __syncthreads();
        }

        // ---- main loop, blocks of PF ----
        for (int i0 = PF; i0 < lenmax; i0 += PF) {
            #pragma unroll
            for (int j = 0; j < PF; j++) {
                const int i = i0 + j;
                const int p = i & 1;
                const bool a1 = (i < len1);      // block-uniform
                const bool a2 = (i < len2);

                float w1 = gs1[p][0];
                float w2 = gs2[p][0];
                float r1 = rcp_fast(w1), r2 = rcp_fast(w2);
                float f1 = ee1[j] * r1,  f2 = ee2[j] * r2;
                ee1[j] = exp2f(emit1[min(i + PF, l1m) * Tdim] * LOG2E);
                ee2[j] = exp2f(emit2[min(i + PF, l2m) * Tdim] * LOG2E);

                float s1 = matvec128(gs1[p], et);
                float s2 = matvec128(gs2[p], et);
                if (a1) { float u = s1 * f1; gs1[p ^ 1][t] = u; G1 = u; Ma1 += __log2f(w1); }
                if (a2) { float u = s2 * f2; gs2[p ^ 1][t] = u; G2 = u; Ma2 += __log2f(w2); }
                __syncthreads();
            }
        }

        // fv[t] = ln2 * (log2(v_len) + Macc); v==0 (START row) -> -inf, OK in LSE
        float fv1 = (__log2f(G1) + Ma1) * LN2;
        float fv2 = (__log2f(G2) + Ma2) * LN2;

        float r1 = finish_batch(fv1, len1, b1, t, lane, warp,
                                feats, trans, tags, smax, ssum);
        float r2 = finish_batch(fv2, len2, b2, t, lane, warp,
                                feats, trans, tags, smax, ssum);
        if (t == 0) {
            g_partial[b1] = r1;
            g_partial[b2] = r2;
            sh_job = atomicAdd(&g_counter, 1);
        }
        __syncthreads();
        job = sh_job;
        __syncthreads();
    }

    // ---- fused final reduction: last CTA to finish computes the mean ----
    __threadfence();
    if (t == 0) sh_last = atomicAdd(&g_done, 1);
    __syncthreads();
    if (sh_last == NWORK - 1) {
        __threadfence();
        float v = 0.f;
        #pragma unroll
        for (int k = 0; k < Bdim / Tdim; k++)
            v += g_partial[k * Tdim + t];
        #pragma unroll
        for (int o = 16; o > 0; o >>= 1)
            v += __shfl_xor_sync(0xffffffffu, v, o);
        if (lane == 0) ssum[warp] = v;
        __syncthreads();
        if (t == 0)
            out[0] = ((ssum[0] + ssum[1]) + (ssum[2] + ssum[3])) * (1.0f / (float)Bdim);
    }
}

extern "C" void kernel_launch(void* const* d_in, const int* in_sizes, int n_in,
                              void* d_out, int out_size)
{
    const float* feats = (const float*)d_in[0];
    const float* trans = (const float*)d_in[1];
    const int*   tags  = (const int*)d_in[2];
    const int*   lens  = (const int*)d_in[3];
    float* out = (float*)d_out;

    crf_schedule_kernel<<<8, 64>>>(lens);
    crf_batch_kernel<<<NWORK, Tdim>>>(feats, trans, tags, lens, out);
}

// round 9
// speedup vs baseline: 1.7078x; 1.4509x over previous
#include <cuda_runtime.h>
#include <string.h>

#define Bdim 512
#define Ldim 512
#define Tdim 128
#define START_TAG 126
#define STOP_TAG 127
#define LOG2E 1.4426950408889634f
#define LN2   0.6931471805599453f
#define PF 8              // emission prefetch depth / unroll factor
#define NWORK 304         // persistent CTAs (2 per SM)

__device__ float g_partial[Bdim];     // per-batch forward - gold
__device__ int   g_counter;           // work queue head
__device__ int   g_done;              // completion counter
__device__ int   g_order[Bdim];       // batch ids sorted by len desc

__device__ __forceinline__ void fma2(unsigned long long& d,
                                     unsigned long long a,
                                     unsigned long long b) {
    asm("fma.rn.f32x2 %0, %1, %2, %0;" : "+l"(d) : "l"(a), "l"(b));
}
__device__ __forceinline__ float rcp_fast(float x) {
    float r;
    asm("rcp.approx.f32 %0, %1;" : "=f"(r) : "f"(x));
    return r;
}
__device__ __forceinline__ unsigned long long pack2(float a, float b) {
    unsigned long long r;
    asm("mov.b64 %0, {%1,%2};" : "=l"(r) : "f"(a), "f"(b));
    return r;
}
__device__ __forceinline__ float hadd2(unsigned long long a) {
    float2 f; memcpy(&f, &a, 8);
    return f.x + f.y;
}

// Warp-split-K matvec: this warp covers p in [32w, 32w+32).
// g = this thread's own state value (lane l of warp w holds g[32w+l]).
// et[64]: rows 4*lane..4*lane+3 (16 pairs each) over this warp's 32 columns.
// Returns partials for states {4*lane, 4*lane+1, 4*lane+2, 4*lane+3}.
__device__ __forceinline__ float4 matvec_warp(float g,
                                              const unsigned long long* et) {
    unsigned long long a0 = 0, a1 = 0, a2 = 0, a3 = 0;
    #pragma unroll
    for (int r = 0; r < 32; r += 2) {
        float ga = __shfl_sync(0xffffffffu, g, r);
        float gb = __shfl_sync(0xffffffffu, g, r + 1);
        unsigned long long gg = pack2(ga, gb);
        const int pp = r >> 1;
        fma2(a0, et[pp],      gg);
        fma2(a1, et[16 + pp], gg);
        fma2(a2, et[32 + pp], gg);
        fma2(a3, et[48 + pp], gg);
    }
    return make_float4(hadd2(a0), hadd2(a1), hadd2(a2), hadd2(a3));
}

// terminal LSE + gold score; returns forward_score - gold_score (all threads)
__device__ __forceinline__ float finish_batch(
    float fv, int len, int b, int t, int lane, int warp,
    const float* __restrict__ feats, const float* __restrict__ trans,
    const int* __restrict__ tags, float* smax, float* ssum)
{
    float term = fv + trans[START_TAG * Tdim + t];
    float m2 = term;
    #pragma unroll
    for (int o = 16; o > 0; o >>= 1)
        m2 = fmaxf(m2, __shfl_xor_sync(0xffffffffu, m2, o));
    if (lane == 0) smax[warp] = m2;
    __syncthreads();
    m2 = fmaxf(fmaxf(smax[0], smax[1]), fmaxf(smax[2], smax[3]));

    float ex = exp2f((term - m2) * LOG2E);
    #pragma unroll
    for (int o = 16; o > 0; o >>= 1)
        ex += __shfl_xor_sync(0xffffffffu, ex, o);
    if (lane == 0) ssum[warp] = ex;
    __syncthreads();
    float fwd = m2 + __logf((ssum[0] + ssum[1]) + (ssum[2] + ssum[3]));
    __syncthreads();

    float acc = 0.f;
    const int* tg = tags + b * Ldim;
    for (int j = t; j <= len; j += Tdim) {
        int pa, pb;
        if (j == 0)        { pa = START_TAG;   pb = tg[0];    }
        else if (j == len) { pa = tg[len - 1]; pb = STOP_TAG; }
        else               { pa = tg[j - 1];   pb = tg[j];    }
        acc += trans[pb * Tdim + pa];
    }
    for (int i = t; i < len; i += Tdim) {
        int tag = tg[i];
        acc += feats[((size_t)b * Ldim + i) * Tdim + tag];
    }
    #pragma unroll
    for (int o = 16; o > 0; o >>= 1)
        acc += __shfl_xor_sync(0xffffffffu, acc, o);
    if (lane == 0) ssum[warp] = acc;
    __syncthreads();
    float gold = (ssum[0] + ssum[1]) + (ssum[2] + ssum[3]);
    __syncthreads();
    return fwd - gold;
}

// rank batches by length (desc, stable) + reset counters. grid 8 x 64
__global__ __launch_bounds__(64) void crf_schedule_kernel(const int* __restrict__ lens)
{
    __shared__ int sl[Bdim];
    const int tb = threadIdx.x;
    for (int k = tb; k < Bdim; k += 64) sl[k] = lens[k];
    __syncthreads();
    const int me = blockIdx.x * 64 + tb;
    const int myl = sl[me];
    int rank = 0;
    #pragma unroll 8
    for (int j = 0; j < Bdim; j++) {
        int lj = sl[j];
        rank += (lj > myl) || (lj == myl && j < me);
    }
    g_order[rank] = me;
    if (me == 0) { g_counter = NWORK; g_done = 0; }
}

__global__ __launch_bounds__(Tdim, 2) void crf_batch_kernel(
    const float* __restrict__ feats,        // [B, L, T]
    const float* __restrict__ trans,        // [T, T]  trans[next, prev]
    const int*   __restrict__ tags,         // [B, L]
    const int*   __restrict__ lens,         // [B]
    float*       __restrict__ out)
{
    const int tid  = threadIdx.x;
    const int lane = tid & 31;
    const int w    = tid >> 5;

    __shared__ __align__(16) float part[2][4 * Tdim]; // partials [buf][w*128+t]
    __shared__ float ubuf[2];                          // normalizer scalar
    __shared__ float smax[4];
    __shared__ float ssum[4];
    __shared__ int   sh_job;
    __shared__ int   sh_last;

    // ---- et: exp(trans) for rows 4*lane..4*lane+3, cols [32w, 32w+32) ----
    unsigned long long et[64];
    #pragma unroll
    for (int tp = 0; tp < 4; tp++) {
        const float4* rowp = reinterpret_cast<const float4*>(
            trans + (4 * lane + tp) * Tdim + 32 * w);
        #pragma unroll
        for (int q = 0; q < 8; q++) {
            float4 v = rowp[q];
            et[tp * 16 + 2 * q]     = pack2(exp2f(v.x * LOG2E), exp2f(v.y * LOG2E));
            et[tp * 16 + 2 * q + 1] = pack2(exp2f(v.z * LOG2E), exp2f(v.w * LOG2E));
        }
    }
    // exp(trans[tid, START]) for the peeled first step
    const float etS = exp2f(trans[tid * Tdim + START_TAG] * LOG2E);

    int job = blockIdx.x;
    while (job < Bdim) {
        const int b     = g_order[job];
        const int len   = lens[b];
        const int lenm1 = len - 1;
        const float* emit = feats + (size_t)b * Ldim * Tdim + tid;

        // emission prefetch ring: ee[k] = exp(emit at step k)
        float ee[PF];
        #pragma unroll
        for (int k = 0; k < PF; k++)
            ee[k] = exp2f(emit[min(k, lenm1) * Tdim] * LOG2E);

        // ---- peel step 0: u_1[t] = ee_0[t] * exp(trans[t, START]), C_1 = 1 ----
        float g    = ee[0] * etS;      // thread tid owns state tid's value
        float Macc = 0.0f;             // accumulated log2 scale
        if (tid == 0) ubuf[1] = g;     // u_1[0], consumed at iter 1 (post-BAR)
        ee[0] = exp2f(emit[min(PF, lenm1) * Tdim] * LOG2E);

        // ---- iterations i = 1 .. PF-1 (peeled ring warm-up) ----
        #pragma unroll
        for (int j = 1; j < PF; j++) {
            const int i = j;
            const int p = i & 1;
            const bool act = (i < len);                  // block-uniform

            float4 s4 = matvec_warp(g, et);
            *reinterpret_cast<float4*>(&part[p][w * Tdim + 4 * lane]) = s4;
            float ecur = ee[j];
            ee[j] = exp2f(emit[min(i + PF, lenm1) * Tdim] * LOG2E);
            __syncthreads();
            float s = (part[p][0 * Tdim + tid] + part[p][1 * Tdim + tid])
                    + (part[p][2 * Tdim + tid] + part[p][3 * Tdim + tid]);
            float wst = ubuf[p];
            float u = s * (ecur * rcp_fast(wst));
            if (act) {
                g = u;
                Macc += __log2f(wst);
                if (tid == 0) ubuf[p ^ 1] = u;
            }
        }

        // ---- main loop, blocks of PF ----
        for (int i0 = PF; i0 < len; i0 += PF) {
            #pragma unroll
            for (int j = 0; j < PF; j++) {
                const int i = i0 + j;
                const int p = i & 1;
                const bool act = (i < len);              // block-uniform

                float4 s4 = matvec_warp(g, et);
                *reinterpret_cast<float4*>(&part[p][w * Tdim + 4 * lane]) = s4;
                float ecur = ee[j];
                ee[j] = exp2f(emit[min(i + PF, lenm1) * Tdim] * LOG2E);
                __syncthreads();
                float s = (part[p][0 * Tdim + tid] + part[p][1 * Tdim + tid])
                        + (part[p][2 * Tdim + tid] + part[p][3 * Tdim + tid]);
                float wst = ubuf[p];
                float u = s * (ecur * rcp_fast(wst));
                if (act) {
                    g = u;
                    Macc += __log2f(wst);
                    if (tid == 0) ubuf[p ^ 1] = u;
                }
            }
        }
        __syncthreads();

        // fv[t] = ln2 * (log2(v_len) + Macc); v==0 (START row) -> -inf, OK in LSE
        float fv = (__log2f(g) + Macc) * LN2;

        float res = finish_batch(fv, len, b, tid, lane, w,
                                 feats, trans, tags, smax, ssum);
        if (tid == 0) {
            g_partial[b] = res;
            sh_job = atomicAdd(&g_counter, 1);
        }
        __syncthreads();
        job = sh_job;
        __syncthreads();
    }

    // ---- fused final reduction: last CTA to finish computes the mean ----
    __threadfence();
    if (tid == 0) sh_last = atomicAdd(&g_done, 1);
    __syncthreads();
    if (sh_last == NWORK - 1) {
        __threadfence();
        float v = 0.f;
        #pragma unroll
        for (int k = 0; k < Bdim / Tdim; k++)
            v += g_partial[k * Tdim + tid];
        #pragma unroll
        for (int o = 16; o > 0; o >>= 1)
            v += __shfl_xor_sync(0xffffffffu, v, o);
        if (lane == 0) ssum[w] = v;
        __syncthreads();
        if (tid == 0)
            out[0] = ((ssum[0] + ssum[1]) + (ssum[2] + ssum[3])) * (1.0f / (float)Bdim);
    }
}

extern "C" void kernel_launch(void* const* d_in, const int* in_sizes, int n_in,
                              void* d_out, int out_size)
{
    const float* feats = (const float*)d_in[0];
    const float* trans = (const float*)d_in[1];
    const int*   tags  = (const int*)d_in[2];
    const int*   lens  = (const int*)d_in[3];
    float* out = (float*)d_out;

    crf_schedule_kernel<<<8, 64>>>(lens);
    crf_batch_kernel<<<NWORK, Tdim>>>(feats, trans, tags, lens, out);
}

// round 10
// speedup vs baseline: 1.8661x; 1.0927x over previous
#include <cuda_runtime.h>
#include <string.h>

#define Bdim 512
#define Ldim 512
#define Tdim 128
#define START_TAG 126
#define STOP_TAG 127
#define LOG2E 1.4426950408889634f
#define LN2   0.6931471805599453f
#define PF 8              // emission prefetch depth / unroll factor
#define NWORK 304         // persistent CTAs (2 per SM)

__device__ float g_partial[Bdim];     // per-batch forward - gold
__device__ int   g_counter;           // work queue head
__device__ int   g_done;              // completion counter
__device__ int   g_order[Bdim];       // batch ids sorted by len desc

__device__ __forceinline__ void fma2(unsigned long long& d,
                                     unsigned long long a,
                                     unsigned long long b) {
    asm("fma.rn.f32x2 %0, %1, %2, %0;" : "+l"(d) : "l"(a), "l"(b));
}
__device__ __forceinline__ float rcp_fast(float x) {
    float r;
    asm("rcp.approx.f32 %0, %1;" : "=f"(r) : "f"(x));
    return r;
}
__device__ __forceinline__ unsigned long long pack2(float a, float b) {
    unsigned long long r;
    asm("mov.b64 %0, {%1,%2};" : "=l"(r) : "f"(a), "f"(b));
    return r;
}
__device__ __forceinline__ float hadd2(unsigned long long a) {
    float2 f; memcpy(&f, &a, 8);
    return f.x + f.y;
}

// Warp-split-K matvec via broadcast LDS from gslice = gbuf + 32*w.
// et[64]: rows 4*lane..4*lane+3 (16 f32x2 pairs each) over this warp's 32 cols.
// Returns partials for states {4*lane .. 4*lane+3}.
__device__ __forceinline__ float4 matvec_warp(const float* gslice,
                                              const unsigned long long* et) {
    const ulonglong2* gb = reinterpret_cast<const ulonglong2*>(gslice);
    unsigned long long a0 = 0, a1 = 0, a2 = 0, a3 = 0;
    #pragma unroll
    for (int q = 0; q < 8; q++) {
        ulonglong2 uv = gb[q];            // broadcast LDS.128
        fma2(a0, et[2 * q],          uv.x);
        fma2(a0, et[2 * q + 1],      uv.y);
        fma2(a1, et[16 + 2 * q],     uv.x);
        fma2(a1, et[16 + 2 * q + 1], uv.y);
        fma2(a2, et[32 + 2 * q],     uv.x);
        fma2(a2, et[32 + 2 * q + 1], uv.y);
        fma2(a3, et[48 + 2 * q],     uv.x);
        fma2(a3, et[48 + 2 * q + 1], uv.y);
    }
    return make_float4(hadd2(a0), hadd2(a1), hadd2(a2), hadd2(a3));
}

// terminal LSE + gold score; returns forward_score - gold_score (all threads)
__device__ __forceinline__ float finish_batch(
    float fv, int len, int b, int t, int lane, int warp,
    const float* __restrict__ feats, const float* __restrict__ trans,
    const int* __restrict__ tags, float* smax, float* ssum)
{
    float term = fv + trans[START_TAG * Tdim + t];
    float m2 = term;
    #pragma unroll
    for (int o = 16; o > 0; o >>= 1)
        m2 = fmaxf(m2, __shfl_xor_sync(0xffffffffu, m2, o));
    if (lane == 0) smax[warp] = m2;
    __syncthreads();
    m2 = fmaxf(fmaxf(smax[0], smax[1]), fmaxf(smax[2], smax[3]));

    float ex = exp2f((term - m2) * LOG2E);
    #pragma unroll
    for (int o = 16; o > 0; o >>= 1)
        ex += __shfl_xor_sync(0xffffffffu, ex, o);
    if (lane == 0) ssum[warp] = ex;
    __syncthreads();
    float fwd = m2 + __logf((ssum[0] + ssum[1]) + (ssum[2] + ssum[3]));
    __syncthreads();

    float acc = 0.f;
    const int* tg = tags + b * Ldim;
    for (int j = t; j <= len; j += Tdim) {
        int pa, pb;
        if (j == 0)        { pa = START_TAG;   pb = tg[0];    }
        else if (j == len) { pa = tg[len - 1]; pb = STOP_TAG; }
        else               { pa = tg[j - 1];   pb = tg[j];    }
        acc += trans[pb * Tdim + pa];
    }
    for (int i = t; i < len; i += Tdim) {
        int tag = tg[i];
        acc += feats[((size_t)b * Ldim + i) * Tdim + tag];
    }
    #pragma unroll
    for (int o = 16; o > 0; o >>= 1)
        acc += __shfl_xor_sync(0xffffffffu, acc, o);
    if (lane == 0) ssum[warp] = acc;
    __syncthreads();
    float gold = (ssum[0] + ssum[1]) + (ssum[2] + ssum[3]);
    __syncthreads();
    return fwd - gold;
}

// rank batches by length (desc, stable) + reset counters. grid 8 x 64
__global__ __launch_bounds__(64) void crf_schedule_kernel(const int* __restrict__ lens)
{
    __shared__ int sl[Bdim];
    const int tb = threadIdx.x;
    for (int k = tb; k < Bdim; k += 64) sl[k] = lens[k];
    __syncthreads();
    const int me = blockIdx.x * 64 + tb;
    const int myl = sl[me];
    int rank = 0;
    #pragma unroll 8
    for (int j = 0; j < Bdim; j++) {
        int lj = sl[j];
        rank += (lj > myl) || (lj == myl && j < me);
    }
    g_order[rank] = me;
    if (me == 0) { g_counter = NWORK; g_done = 0; }
}

__global__ __launch_bounds__(Tdim, 2) void crf_batch_kernel(
    const float* __restrict__ feats,        // [B, L, T]
    const float* __restrict__ trans,        // [T, T]  trans[next, prev]
    const int*   __restrict__ tags,         // [B, L]
    const int*   __restrict__ lens,         // [B]
    float*       __restrict__ out)
{
    const int tid  = threadIdx.x;
    const int lane = tid & 31;
    const int w    = tid >> 5;

    __shared__ __align__(16) float gbuf[2][Tdim];      // unnormalized u, dbl-buffered
    __shared__ __align__(16) float part[2][4 * Tdim];  // partials [buf][w*128 + t]
    __shared__ float smax[4];
    __shared__ float ssum[4];
    __shared__ int   sh_job;
    __shared__ int   sh_last;

    // ---- et: exp(trans) for rows 4*lane..4*lane+3, cols [32w, 32w+32) ----
    unsigned long long et[64];
    #pragma unroll
    for (int tp = 0; tp < 4; tp++) {
        const float4* rowp = reinterpret_cast<const float4*>(
            trans + (4 * lane + tp) * Tdim + 32 * w);
        #pragma unroll
        for (int q = 0; q < 8; q++) {
            float4 v = rowp[q];
            et[tp * 16 + 2 * q]     = pack2(exp2f(v.x * LOG2E), exp2f(v.y * LOG2E));
            et[tp * 16 + 2 * q + 1] = pack2(exp2f(v.z * LOG2E), exp2f(v.w * LOG2E));
        }
    }
    // exp(trans[tid, START]) for the peeled first step
    const float etS = exp2f(trans[tid * Tdim + START_TAG] * LOG2E);

    int job = blockIdx.x;
    while (job < Bdim) {
        const int b     = g_order[job];
        const int len   = lens[b];
        const int lenm1 = len - 1;
        const float* emit = feats + (size_t)b * Ldim * Tdim + tid;

        // emission prefetch ring: ee[k] = exp(emit at step k)
        float ee[PF];
        #pragma unroll
        for (int k = 0; k < PF; k++)
            ee[k] = exp2f(emit[min(k, lenm1) * Tdim] * LOG2E);

        // ---- peel step 0: u_1[t] = ee_0[t] * exp(trans[t, START]), C_1 = 1 ----
        float g    = ee[0] * etS;
        float Macc = 0.0f;                   // accumulated log2 scale
        gbuf[1][tid] = g;                    // step i reads gbuf[i&1]
        ee[0] = exp2f(emit[min(PF, lenm1) * Tdim] * LOG2E);
        __syncthreads();

        // ---- iterations i = 1 .. PF-1 (ring warm-up) ----
        #pragma unroll
        for (int j = 1; j < PF; j++) {
            const int i = j;
            const int p = i & 1;
            const bool act = (i < len);                  // block-uniform

            float w0 = gbuf[p][0];                       // normalizer (broadcast)
            float4 s4 = matvec_warp(&gbuf[p][32 * w], et);
            *reinterpret_cast<float4*>(&part[p][w * Tdim + 4 * lane]) = s4;
            float ecur = ee[j];
            ee[j] = exp2f(emit[min(i + PF, lenm1) * Tdim] * LOG2E);
            __syncthreads();                             // partials ready
            float s = (part[p][0 * Tdim + tid] + part[p][1 * Tdim + tid])
                    + (part[p][2 * Tdim + tid] + part[p][3 * Tdim + tid]);
            float u = s * (ecur * rcp_fast(w0));
            if (act) {
                g = u;
                Macc += __log2f(w0);
                gbuf[p ^ 1][tid] = u;
            }
            __syncthreads();                             // gbuf published
        }

        // ---- main loop, blocks of PF ----
        for (int i0 = PF; i0 < len; i0 += PF) {
            #pragma unroll
            for (int j = 0; j < PF; j++) {
                const int i = i0 + j;
                const int p = i & 1;
                const bool act = (i < len);              // block-uniform

                float w0 = gbuf[p][0];
                float4 s4 = matvec_warp(&gbuf[p][32 * w], et);
                *reinterpret_cast<float4*>(&part[p][w * Tdim + 4 * lane]) = s4;
                float ecur = ee[j];
                ee[j] = exp2f(emit[min(i + PF, lenm1) * Tdim] * LOG2E);
                __syncthreads();
                float s = (part[p][0 * Tdim + tid] + part[p][1 * Tdim + tid])
                        + (part[p][2 * Tdim + tid] + part[p][3 * Tdim + tid]);
                float u = s * (ecur * rcp_fast(w0));
                if (act) {
                    g = u;
                    Macc += __log2f(w0);
                    gbuf[p ^ 1][tid] = u;
                }
                __syncthreads();
            }
        }

        // fv[t] = ln2 * (log2(u_len) + Macc); u==0 (START row) -> -inf, OK in LSE
        float fv = (__log2f(g) + Macc) * LN2;

        float res = finish_batch(fv, len, b, tid, lane, w,
                                 feats, trans, tags, smax, ssum);
        if (tid == 0) {
            g_partial[b] = res;
            sh_job = atomicAdd(&g_counter, 1);
        }
        __syncthreads();
        job = sh_job;
        __syncthreads();
    }

    // ---- fused final reduction: last CTA to finish computes the mean ----
    __threadfence();
    if (tid == 0) sh_last = atomicAdd(&g_done, 1);
    __syncthreads();
    if (sh_last == NWORK - 1) {
        __threadfence();
        float v = 0.f;
        #pragma unroll
        for (int k = 0; k < Bdim / Tdim; k++)
            v += g_partial[k * Tdim + tid];
        #pragma unroll
        for (int o = 16; o > 0; o >>= 1)
            v += __shfl_xor_sync(0xffffffffu, v, o);
        if (lane == 0) ssum[w] = v;
        __syncthreads();
        if (tid == 0)
            out[0] = ((ssum[0] + ssum[1]) + (ssum[2] + ssum[3])) * (1.0f / (float)Bdim);
    }
}

extern "C" void kernel_launch(void* const* d_in, const int* in_sizes, int n_in,
                              void* d_out, int out_size)
{
    const float* feats = (const float*)d_in[0];
    const float* trans = (const float*)d_in[1];
    const int*   tags  = (const int*)d_in[2];
    const int*   lens  = (const int*)d_in[3];
    float* out = (float*)d_out;

    crf_schedule_kernel<<<8, 64>>>(lens);
    crf_batch_kernel<<<NWORK, Tdim>>>(feats, trans, tags, lens, out);
}